// round 6
// baseline (speedup 1.0000x reference)
#include <cuda_runtime.h>
#include <cuda_fp16.h>

// Problem constants
#define BATCH 256
#define HWDIM 128
#define OCN   16
#define PO    63            // pooled spatial dim
#define FTOT  63504         // 16*63*63
#define NHID  256
#define FANIN 512
#define NOUT  10

// Scratch (static device arrays per allocation rules)
__device__ float  g_feats[(size_t)BATCH * FTOT];    // pooled feats, [b][f] fp32
__device__ __half g_feats_T[(size_t)FTOT * BATCH];  // transposed,   [f][b] fp16
__device__ float  g_hidden[BATCH * NHID];           // hidden,       [b][h]

// ============================================================
// Kernel A: conv3x3 (VALID) + bias + relu + maxpool2x2 -> g_feats[b][f]
// One pooled point per thread, tap-major inner loop (validated ~134us, 72%
// of scalar-FFMA roofline). Grid: (9, 256) x 448 thr, launch_bounds(448,2).
// ============================================================
__global__ __launch_bounds__(448, 2) void conv_pool_kernel(
    const float* __restrict__ in,
    const float* __restrict__ cw,
    const float* __restrict__ cb)
{
    __shared__ float s_in[3 * 44 * 44];
    __shared__ float s_w[27][16];      // [tap][oc]; row = 64B, 16B-aligned
    __shared__ float s_b[16];

    const int tile = blockIdx.x;       // 0..8
    const int b    = blockIdx.y;
    const int ty   = tile / 3, tx = tile % 3;
    const int tid  = threadIdx.x;

    if (tid < 432) {
        int oc = tid / 27, widx = tid % 27;   // conv_w is [16][27] contiguous
        s_w[widx][oc] = cw[tid];
    }
    if (tid < 16) s_b[tid] = cb[tid];

    const int iy0 = 42 * ty, ix0 = 42 * tx;
    for (int i = tid; i < 3 * 44 * 44; i += 448) {
        int c = i / 1936;
        int r = (i % 1936) / 44;
        int x = i % 44;
        s_in[i] = in[(((size_t)b * 3 + c) * HWDIM + (iy0 + r)) * HWDIM + (ix0 + x)];
    }
    __syncthreads();

    if (tid >= 441) return;
    const int lpy = tid / 21, lpx = tid % 21;
    const int py  = ty * 21 + lpy, px = tx * 21 + lpx;
    float* frow = &g_feats[(size_t)b * FTOT + py * PO + px];

    #pragma unroll
    for (int g = 0; g < 2; g++) {          // 8 output channels per pass
        float acc[4][8];                   // [conv sub-pixel][oc]
        #pragma unroll
        for (int p4 = 0; p4 < 4; p4++)
            #pragma unroll
            for (int o = 0; o < 8; o++) acc[p4][o] = 0.0f;

        #pragma unroll
        for (int c = 0; c < 3; c++) {
            float win[4][4];
            #pragma unroll
            for (int yy = 0; yy < 4; yy++) {
                const float* rp = &s_in[c * 1936 + (2 * lpy + yy) * 44 + 2 * lpx];
                float2 v0 = *(const float2*)rp;       // 8B-aligned (2*lpx even)
                float2 v1 = *(const float2*)(rp + 2);
                win[yy][0] = v0.x; win[yy][1] = v0.y;
                win[yy][2] = v1.x; win[yy][3] = v1.y;
            }

            #pragma unroll
            for (int ky = 0; ky < 3; ky++) {
                #pragma unroll
                for (int kx = 0; kx < 3; kx++) {
                    const float4* wp = (const float4*)&s_w[c * 9 + ky * 3 + kx][g * 8];
                    float4 wA = wp[0];                // broadcast LDS.128
                    float4 wB = wp[1];
                    #pragma unroll
                    for (int sy = 0; sy < 2; sy++) {
                        #pragma unroll
                        for (int sx = 0; sx < 2; sx++) {
                            float a = win[ky + sy][kx + sx];
                            float* ac = acc[sy * 2 + sx];
                            ac[0] = fmaf(a, wA.x, ac[0]);
                            ac[1] = fmaf(a, wA.y, ac[1]);
                            ac[2] = fmaf(a, wA.z, ac[2]);
                            ac[3] = fmaf(a, wA.w, ac[3]);
                            ac[4] = fmaf(a, wB.x, ac[4]);
                            ac[5] = fmaf(a, wB.y, ac[5]);
                            ac[6] = fmaf(a, wB.z, ac[6]);
                            ac[7] = fmaf(a, wB.w, ac[7]);
                        }
                    }
                }
            }
        }

        #pragma unroll
        for (int o = 0; o < 8; o++) {
            float m = fmaxf(fmaxf(acc[0][o], acc[1][o]),
                            fmaxf(acc[2][o], acc[3][o]));
            float v = fmaxf(m + s_b[g * 8 + o], 0.0f);  // max(relu)==relu(max)+b
            frow[(size_t)(g * 8 + o) * (PO * PO)] = v;
        }
    }
}

// ============================================================
// Kernel T: transpose g_feats[b][f] (fp32) -> g_feats_T[f][b] (fp16).
// 32x32 smem tiles; coalesced reads, 64B-contiguous fp16 warp writes.
// ============================================================
__global__ __launch_bounds__(256) void transpose_kernel()
{
    __shared__ float t[32][33];
    const int f0 = blockIdx.x * 32, b0 = blockIdx.y * 32;
    const int tx = threadIdx.x & 31, ty = threadIdx.x >> 5;   // 32 x 8

    #pragma unroll
    for (int j = 0; j < 4; j++) {
        int f = f0 + tx;
        int b = b0 + ty + 8 * j;
        t[ty + 8 * j][tx] = (f < FTOT) ? g_feats[(size_t)b * FTOT + f] : 0.0f;
    }
    __syncthreads();
    #pragma unroll
    for (int j = 0; j < 4; j++) {
        int f = f0 + ty + 8 * j;
        int b = b0 + tx;
        if (f < FTOT)
            g_feats_T[(size_t)f * BATCH + b] = __float2half_rn(t[tx][ty + 8 * j]);
    }
}

// ============================================================
// Kernel B: hidden[b][h] = sigmoid(sum_k feats_T[idx[h,k]][b]*w[h,k]+hb[h])
// One CTA per h, 512 threads = (k-half, batch). Pairs staged once per h;
// every feat load is a coalesced 64B fp16 warp access (L2-resident).
// ============================================================
__global__ __launch_bounds__(512) void gather_hidden_kernel(
    const int*   __restrict__ hidx,
    const float* __restrict__ hw,
    const float* __restrict__ hb)
{
    __shared__ int   s_idx[FANIN];
    __shared__ float s_w[FANIN];
    __shared__ float s_part[BATCH];

    const int h   = blockIdx.x;
    const int tid = threadIdx.x;

    s_idx[tid] = hidx[h * FANIN + tid];
    s_w[tid]   = hw[h * FANIN + tid];
    __syncthreads();

    const int b    = tid & 255;
    const int half = tid >> 8;         // 0/1
    const int k0   = half * 256;

    float acc = 0.0f;
    #pragma unroll 8
    for (int k = 0; k < 256; k++) {
        int idx = s_idx[k0 + k];       // broadcast LDS
        float f = __half2float(g_feats_T[(size_t)idx * BATCH + b]);
        acc = fmaf(f, s_w[k0 + k], acc);
    }

    if (half) s_part[b] = acc;
    __syncthreads();
    if (!half) {
        float tot = acc + s_part[b];
        g_hidden[b * NHID + h] = 1.0f / (1.0f + expf(-(tot + hb[h])));
    }
}

// ============================================================
// Kernel C: out = sigmoid(hidden @ out_w^T + out_b)   [256 x 10]
// R2-validated shape (4.9us): one CTA per batch, one warp per output,
// coalesced reads of g_hidden row.
// ============================================================
__global__ __launch_bounds__(320) void out_kernel(
    const float* __restrict__ ow,
    const float* __restrict__ ob,
    float* __restrict__ out)
{
    const int b = blockIdx.x;
    const int warp = threadIdx.x >> 5, lane = threadIdx.x & 31;
    if (warp < NOUT) {
        float acc = 0.f;
        #pragma unroll
        for (int i = 0; i < NHID / 32; i++) {
            int j = i * 32 + lane;
            acc = fmaf(g_hidden[b * NHID + j], ow[warp * NHID + j], acc);
        }
        #pragma unroll
        for (int s = 16; s; s >>= 1) acc += __shfl_xor_sync(0xffffffffu, acc, s);
        if (lane == 0)
            out[b * NOUT + warp] = 1.f / (1.f + expf(-(acc + ob[warp])));
    }
}

// ============================================================
extern "C" void kernel_launch(void* const* d_in, const int* in_sizes, int n_in,
                              void* d_out, int out_size)
{
    const float* inputs = (const float*)d_in[0];
    const float* conv_w = (const float*)d_in[1];
    const float* conv_b = (const float*)d_in[2];
    const int*   hidx   = (const int*)d_in[3];
    const float* hw     = (const float*)d_in[4];
    const float* hb     = (const float*)d_in[5];
    const float* ow     = (const float*)d_in[6];
    const float* ob     = (const float*)d_in[7];

    conv_pool_kernel<<<dim3(9, BATCH), 448>>>(inputs, conv_w, conv_b);
    transpose_kernel<<<dim3((FTOT + 31) / 32, BATCH / 32), 256>>>();
    gather_hidden_kernel<<<NHID, 512>>>(hidx, hw, hb);
    out_kernel<<<BATCH, 320>>>(ow, ob, (float*)d_out);
}

// round 7
// speedup vs baseline: 1.3863x; 1.3863x over previous
#include <cuda_runtime.h>

// Problem constants
#define BATCH 256
#define HWDIM 128
#define OCN   16
#define PO    63            // pooled spatial dim
#define FTOT  63504         // 16*63*63
#define NHID  256
#define FANIN 512
#define NOUT  10

// Scratch (static device arrays per allocation rules)
__device__ float g_feats[(size_t)BATCH * FTOT];    // pooled feats, [b][f]
__device__ float g_feats_T[(size_t)FTOT * BATCH];  // transposed,   [f][b]
__device__ float g_hidden[BATCH * NHID];           // hidden,       [b][h]

// ============================================================
// Kernel A: conv3x3 (VALID) + bias + relu + maxpool2x2 -> g_feats[b][f]
// One pooled point per thread, tap-major inner loop (measured ~134us, 72%
// of scalar-FFMA roofline). Grid: (9, 256) x 448 thr, launch_bounds(448,2).
// ============================================================
__global__ __launch_bounds__(448, 2) void conv_pool_kernel(
    const float* __restrict__ in,
    const float* __restrict__ cw,
    const float* __restrict__ cb)
{
    __shared__ float s_in[3 * 44 * 44];
    __shared__ float s_w[27][16];      // [tap][oc]; row = 64B, 16B-aligned
    __shared__ float s_b[16];

    const int tile = blockIdx.x;       // 0..8
    const int b    = blockIdx.y;
    const int ty   = tile / 3, tx = tile % 3;
    const int tid  = threadIdx.x;

    if (tid < 432) {
        int oc = tid / 27, widx = tid % 27;   // conv_w is [16][27] contiguous
        s_w[widx][oc] = cw[tid];
    }
    if (tid < 16) s_b[tid] = cb[tid];

    const int iy0 = 42 * ty, ix0 = 42 * tx;
    for (int i = tid; i < 3 * 44 * 44; i += 448) {
        int c = i / 1936;
        int r = (i % 1936) / 44;
        int x = i % 44;
        s_in[i] = in[(((size_t)b * 3 + c) * HWDIM + (iy0 + r)) * HWDIM + (ix0 + x)];
    }
    __syncthreads();

    if (tid >= 441) return;
    const int lpy = tid / 21, lpx = tid % 21;
    const int py  = ty * 21 + lpy, px = tx * 21 + lpx;
    float* frow = &g_feats[(size_t)b * FTOT + py * PO + px];

    #pragma unroll
    for (int g = 0; g < 2; g++) {          // 8 output channels per pass
        float acc[4][8];                   // [conv sub-pixel][oc]
        #pragma unroll
        for (int p4 = 0; p4 < 4; p4++)
            #pragma unroll
            for (int o = 0; o < 8; o++) acc[p4][o] = 0.0f;

        #pragma unroll
        for (int c = 0; c < 3; c++) {
            float win[4][4];
            #pragma unroll
            for (int yy = 0; yy < 4; yy++) {
                const float* rp = &s_in[c * 1936 + (2 * lpy + yy) * 44 + 2 * lpx];
                float2 v0 = *(const float2*)rp;       // 8B-aligned (2*lpx even)
                float2 v1 = *(const float2*)(rp + 2);
                win[yy][0] = v0.x; win[yy][1] = v0.y;
                win[yy][2] = v1.x; win[yy][3] = v1.y;
            }

            #pragma unroll
            for (int ky = 0; ky < 3; ky++) {
                #pragma unroll
                for (int kx = 0; kx < 3; kx++) {
                    const float4* wp = (const float4*)&s_w[c * 9 + ky * 3 + kx][g * 8];
                    float4 wA = wp[0];                // broadcast LDS.128
                    float4 wB = wp[1];
                    #pragma unroll
                    for (int sy = 0; sy < 2; sy++) {
                        #pragma unroll
                        for (int sx = 0; sx < 2; sx++) {
                            float a = win[ky + sy][kx + sx];
                            float* ac = acc[sy * 2 + sx];
                            ac[0] = fmaf(a, wA.x, ac[0]);
                            ac[1] = fmaf(a, wA.y, ac[1]);
                            ac[2] = fmaf(a, wA.z, ac[2]);
                            ac[3] = fmaf(a, wA.w, ac[3]);
                            ac[4] = fmaf(a, wB.x, ac[4]);
                            ac[5] = fmaf(a, wB.y, ac[5]);
                            ac[6] = fmaf(a, wB.z, ac[6]);
                            ac[7] = fmaf(a, wB.w, ac[7]);
                        }
                    }
                }
            }
        }

        #pragma unroll
        for (int o = 0; o < 8; o++) {
            float m = fmaxf(fmaxf(acc[0][o], acc[1][o]),
                            fmaxf(acc[2][o], acc[3][o]));
            float v = fmaxf(m + s_b[g * 8 + o], 0.0f);  // max(relu)==relu(max)+b
            frow[(size_t)(g * 8 + o) * (PO * PO)] = v;
        }
    }
}

// ============================================================
// Kernel T: transpose g_feats[b][f] -> g_feats_T[f][b], fp32 (measured 11us).
// 32x32 smem tiles; both sides coalesced.
// ============================================================
__global__ __launch_bounds__(256) void transpose_kernel()
{
    __shared__ float t[32][33];
    const int f0 = blockIdx.x * 32, b0 = blockIdx.y * 32;
    const int tx = threadIdx.x & 31, ty = threadIdx.x >> 5;   // 32 x 8

    #pragma unroll
    for (int j = 0; j < 4; j++) {
        int f = f0 + tx;
        int b = b0 + ty + 8 * j;
        t[ty + 8 * j][tx] = (f < FTOT) ? g_feats[(size_t)b * FTOT + f] : 0.0f;
    }
    __syncthreads();
    #pragma unroll
    for (int j = 0; j < 4; j++) {
        int f = f0 + ty + 8 * j;
        int b = b0 + tx;
        if (f < FTOT) g_feats_T[(size_t)f * BATCH + b] = t[tx][ty + 8 * j];
    }
}

// ============================================================
// Kernel B: hidden[b][h] = sigmoid(sum_k feats_T[idx[h,k]][b]*w[h,k]+hb[h])
// One CTA per h, 512 threads = (k-half, batch); fp32 coalesced 128B warp
// loads from L2-resident feats_T (measured ~13us in this form).
// Row-major hidden store is scattered but tiny (2MB total).
// ============================================================
__global__ __launch_bounds__(512) void gather_hidden_kernel(
    const int*   __restrict__ hidx,
    const float* __restrict__ hw,
    const float* __restrict__ hb)
{
    __shared__ int   s_idx[FANIN];
    __shared__ float s_w[FANIN];
    __shared__ float s_part[BATCH];

    const int h   = blockIdx.x;
    const int tid = threadIdx.x;

    s_idx[tid] = hidx[h * FANIN + tid];
    s_w[tid]   = hw[h * FANIN + tid];
    __syncthreads();

    const int b    = tid & 255;
    const int half = tid >> 8;         // 0/1
    const int k0   = half * 256;

    float acc = 0.0f;
    #pragma unroll 8
    for (int k = 0; k < 256; k++) {
        int idx = s_idx[k0 + k];       // broadcast LDS
        acc = fmaf(g_feats_T[(size_t)idx * BATCH + b], s_w[k0 + k], acc);
    }

    if (half) s_part[b] = acc;
    __syncthreads();
    if (!half) {
        float tot = acc + s_part[b];
        g_hidden[b * NHID + h] = 1.0f / (1.0f + expf(-(tot + hb[h])));
    }
}

// ============================================================
// Kernel C: out = sigmoid(hidden @ out_w^T + out_b)   [256 x 10]
// Measured-fast shape (6.2us): one CTA per batch, one warp per output,
// coalesced reads of the g_hidden row.
// ============================================================
__global__ __launch_bounds__(320) void out_kernel(
    const float* __restrict__ ow,
    const float* __restrict__ ob,
    float* __restrict__ out)
{
    const int b = blockIdx.x;
    const int warp = threadIdx.x >> 5, lane = threadIdx.x & 31;
    if (warp < NOUT) {
        float acc = 0.f;
        #pragma unroll
        for (int i = 0; i < NHID / 32; i++) {
            int j = i * 32 + lane;
            acc = fmaf(g_hidden[b * NHID + j], ow[warp * NHID + j], acc);
        }
        #pragma unroll
        for (int s = 16; s; s >>= 1) acc += __shfl_xor_sync(0xffffffffu, acc, s);
        if (lane == 0)
            out[b * NOUT + warp] = 1.f / (1.f + expf(-(acc + ob[warp])));
    }
}

// ============================================================
extern "C" void kernel_launch(void* const* d_in, const int* in_sizes, int n_in,
                              void* d_out, int out_size)
{
    const float* inputs = (const float*)d_in[0];
    const float* conv_w = (const float*)d_in[1];
    const float* conv_b = (const float*)d_in[2];
    const int*   hidx   = (const int*)d_in[3];
    const float* hw     = (const float*)d_in[4];
    const float* hb     = (const float*)d_in[5];
    const float* ow     = (const float*)d_in[6];
    const float* ob     = (const float*)d_in[7];

    conv_pool_kernel<<<dim3(9, BATCH), 448>>>(inputs, conv_w, conv_b);
    transpose_kernel<<<dim3((FTOT + 31) / 32, BATCH / 32), 256>>>();
    gather_hidden_kernel<<<NHID, 512>>>(hidx, hw, hb);
    out_kernel<<<BATCH, 320>>>(ow, ob, (float*)d_out);
}

// round 8
// speedup vs baseline: 1.4114x; 1.0181x over previous
#include <cuda_runtime.h>
#include <cuda_fp16.h>

// Problem constants
#define BATCH 256
#define HWDIM 128
#define OCN   16
#define PO    63            // pooled spatial dim
#define FTOT  63504         // 16*63*63
#define NHID  256
#define FANIN 512
#define NOUT  10

// Scratch (static device arrays per allocation rules)
__device__ float g_feats[(size_t)BATCH * FTOT];    // pooled feats, [b][f]
__device__ float g_feats_T[(size_t)FTOT * BATCH];  // transposed,   [f][b]
__device__ float g_hidden[BATCH * NHID];           // hidden,       [b][h]

// ============================================================
// Kernel A: conv3x3 (VALID) + bias + relu + maxpool2x2 -> g_feats[b][f]
// HFMA2 version: fp16 lanes = the two POOL ROWS (sy=0/1).
//   smem h2[c][r][x] = {in[c][r][x], in[c][r+1][x]}  (packed once from fp32)
//   weights {w,w};  acc = half2 acc[sx][16 oc]  (sx = pool column 0/1)
// Per thread: 864 HFMA2 (was 1728 FFMA) -> pipe floor halves.
// Bias/relu/store in fp32. Grid: (9, 256) x 448 thr, launch_bounds(448,2).
// ============================================================
__global__ __launch_bounds__(448, 2) void conv_pool_kernel(
    const float* __restrict__ in,
    const float* __restrict__ cw,
    const float* __restrict__ cb)
{
    __shared__ float   s_in[3 * 44 * 44];       // 23.2 KB fp32 staging
    __shared__ __half2 s_h2[3][43][44];         // 22.2 KB row-pair packed
    __shared__ __half2 s_w[27][16];             // [tap][oc] = {w,w}
    __shared__ float   s_b[16];

    const int tile = blockIdx.x;       // 0..8
    const int b    = blockIdx.y;
    const int ty   = tile / 3, tx = tile % 3;
    const int tid  = threadIdx.x;

    if (tid < 432) {
        int oc = tid / 27, widx = tid % 27;     // conv_w is [16][27] contiguous
        s_w[widx][oc] = __float2half2_rn(cw[tid]);
    }
    if (tid < 16) s_b[tid] = cb[tid];

    const int iy0 = 42 * ty, ix0 = 42 * tx;
    for (int i = tid; i < 3 * 44 * 44; i += 448) {
        int c = i / 1936;
        int r = (i % 1936) / 44;
        int x = i % 44;
        s_in[i] = in[(((size_t)b * 3 + c) * HWDIM + (iy0 + r)) * HWDIM + (ix0 + x)];
    }
    __syncthreads();

    // pack row pairs: h2[c][r][x] = {in[r][x], in[r+1][x]}
    for (int i = tid; i < 3 * 43 * 44; i += 448) {
        int c = i / (43 * 44);
        int r = (i % (43 * 44)) / 44;
        int x = i % 44;
        const float* p = &s_in[c * 1936 + r * 44 + x];
        s_h2[c][r][x] = __floats2half2_rn(p[0], p[44]);
    }
    __syncthreads();

    if (tid >= 441) return;
    const int lpy = tid / 21, lpx = tid % 21;
    const int py  = ty * 21 + lpy, px = tx * 21 + lpx;
    float* frow = &g_feats[(size_t)b * FTOT + py * PO + px];

    __half2 acc0[16], acc1[16];        // [oc]; acc0: sx=0, acc1: sx=1
    const __half2 z = __floats2half2_rn(0.f, 0.f);
    #pragma unroll
    for (int o = 0; o < 16; o++) { acc0[o] = z; acc1[o] = z; }

    #pragma unroll
    for (int c = 0; c < 3; c++) {
        #pragma unroll
        for (int ky = 0; ky < 3; ky++) {
            #pragma unroll
            for (int kx = 0; kx < 3; kx++) {
                // lanes carry rows (2*lpy+ky, 2*lpy+ky+1) = sy 0/1
                __half2 a0 = s_h2[c][2 * lpy + ky][2 * lpx + kx];
                __half2 a1 = s_h2[c][2 * lpy + ky][2 * lpx + kx + 1];

                __half2 w[16];
                const float4* wp = (const float4*)s_w[c * 9 + ky * 3 + kx];
                *(float4*)&w[0]  = wp[0];   // 4x broadcast LDS.128
                *(float4*)&w[4]  = wp[1];
                *(float4*)&w[8]  = wp[2];
                *(float4*)&w[12] = wp[3];

                #pragma unroll
                for (int o = 0; o < 16; o++) {
                    acc0[o] = __hfma2(a0, w[o], acc0[o]);
                    acc1[o] = __hfma2(a1, w[o], acc1[o]);
                }
            }
        }
    }

    #pragma unroll
    for (int o = 0; o < 16; o++) {
        __half2 mh = __hmax2(acc0[o], acc1[o]);            // max over sx
        float m = fmaxf(__half2float(__low2half(mh)),      // max over sy
                        __half2float(__high2half(mh)));
        float v = fmaxf(m + s_b[o], 0.0f);  // max(relu)==relu(max)+b, fp32
        frow[(size_t)o * (PO * PO)] = v;
    }
}

// ============================================================
// Kernel T: transpose g_feats[b][f] -> g_feats_T[f][b], fp32 (measured 11us).
// 32x32 smem tiles; both sides coalesced.
// ============================================================
__global__ __launch_bounds__(256) void transpose_kernel()
{
    __shared__ float t[32][33];
    const int f0 = blockIdx.x * 32, b0 = blockIdx.y * 32;
    const int tx = threadIdx.x & 31, ty = threadIdx.x >> 5;   // 32 x 8

    #pragma unroll
    for (int j = 0; j < 4; j++) {
        int f = f0 + tx;
        int b = b0 + ty + 8 * j;
        t[ty + 8 * j][tx] = (f < FTOT) ? g_feats[(size_t)b * FTOT + f] : 0.0f;
    }
    __syncthreads();
    #pragma unroll
    for (int j = 0; j < 4; j++) {
        int f = f0 + ty + 8 * j;
        int b = b0 + tx;
        if (f < FTOT) g_feats_T[(size_t)f * BATCH + b] = t[tx][ty + 8 * j];
    }
}

// ============================================================
// Kernel B: hidden[b][h] = sigmoid(sum_k feats_T[idx[h,k]][b]*w[h,k]+hb[h])
// One CTA per h, 512 threads = (k-half, batch); fp32 coalesced 128B warp
// loads from L2-resident feats_T (measured ~13us in this form).
// ============================================================
__global__ __launch_bounds__(512) void gather_hidden_kernel(
    const int*   __restrict__ hidx,
    const float* __restrict__ hw,
    const float* __restrict__ hb)
{
    __shared__ int   s_idx[FANIN];
    __shared__ float s_w[FANIN];
    __shared__ float s_part[BATCH];

    const int h   = blockIdx.x;
    const int tid = threadIdx.x;

    s_idx[tid] = hidx[h * FANIN + tid];
    s_w[tid]   = hw[h * FANIN + tid];
    __syncthreads();

    const int b    = tid & 255;
    const int half = tid >> 8;         // 0/1
    const int k0   = half * 256;

    float acc = 0.0f;
    #pragma unroll 8
    for (int k = 0; k < 256; k++) {
        int idx = s_idx[k0 + k];       // broadcast LDS
        acc = fmaf(g_feats_T[(size_t)idx * BATCH + b], s_w[k0 + k], acc);
    }

    if (half) s_part[b] = acc;
    __syncthreads();
    if (!half) {
        float tot = acc + s_part[b];
        g_hidden[b * NHID + h] = 1.0f / (1.0f + expf(-(tot + hb[h])));
    }
}

// ============================================================
// Kernel C: out = sigmoid(hidden @ out_w^T + out_b)   [256 x 10]
// Measured-fast shape (4.7us): one CTA per batch, one warp per output.
// ============================================================
__global__ __launch_bounds__(320) void out_kernel(
    const float* __restrict__ ow,
    const float* __restrict__ ob,
    float* __restrict__ out)
{
    const int b = blockIdx.x;
    const int warp = threadIdx.x >> 5, lane = threadIdx.x & 31;
    if (warp < NOUT) {
        float acc = 0.f;
        #pragma unroll
        for (int i = 0; i < NHID / 32; i++) {
            int j = i * 32 + lane;
            acc = fmaf(g_hidden[b * NHID + j], ow[warp * NHID + j], acc);
        }
        #pragma unroll
        for (int s = 16; s; s >>= 1) acc += __shfl_xor_sync(0xffffffffu, acc, s);
        if (lane == 0)
            out[b * NOUT + warp] = 1.f / (1.f + expf(-(acc + ob[warp])));
    }
}

// ============================================================
extern "C" void kernel_launch(void* const* d_in, const int* in_sizes, int n_in,
                              void* d_out, int out_size)
{
    const float* inputs = (const float*)d_in[0];
    const float* conv_w = (const float*)d_in[1];
    const float* conv_b = (const float*)d_in[2];
    const int*   hidx   = (const int*)d_in[3];
    const float* hw     = (const float*)d_in[4];
    const float* hb     = (const float*)d_in[5];
    const float* ow     = (const float*)d_in[6];
    const float* ob     = (const float*)d_in[7];

    conv_pool_kernel<<<dim3(9, BATCH), 448>>>(inputs, conv_w, conv_b);
    transpose_kernel<<<dim3((FTOT + 31) / 32, BATCH / 32), 256>>>();
    gather_hidden_kernel<<<NHID, 512>>>(hidx, hw, hb);
    out_kernel<<<BATCH, 320>>>(ow, ob, (float*)d_out);
}